// round 16
// baseline (speedup 1.0000x reference)
#include <cuda_runtime.h>
#include <cuda_bf16.h>
#include <math.h>
#include <stdint.h>

#define B_  2
#define T_  2048
#define D_  1024
#define H_  4
#define BT_ 4096

typedef unsigned long long ull;

// ---- packed f32x2 helpers ---------------------------------------------------
__device__ __forceinline__ ull pk2(float lo, float hi) {
    ull r; asm("mov.b64 %0, {%1, %2};" : "=l"(r) : "f"(lo), "f"(hi)); return r;
}
__device__ __forceinline__ void ffma2(ull &c, ull a, ull b) {
    asm("fma.rn.f32x2 %0, %1, %2, %0;" : "+l"(c) : "l"(a), "l"(b));
}
__device__ __forceinline__ void fmul2(ull &c, ull f) {
    asm("mul.rn.f32x2 %0, %0, %1;" : "+l"(c) : "l"(f));
}
__device__ __forceinline__ void upk2(ull v, float &lo, float &hi) {
    asm("mov.b64 {%0, %1}, %2;" : "=f"(lo), "=f"(hi) : "l"(v));
}

// ---- mma.sync / ldmatrix / cp.async helpers (arch-portable sm_80+) ----------
__device__ __forceinline__ uint32_t smem_u32(const void* p) {
    uint32_t a;
    asm("{ .reg .u64 t; cvta.to.shared.u64 t, %1; cvt.u32.u64 %0, t; }"
        : "=r"(a) : "l"(p));
    return a;
}
__device__ __forceinline__ void ldsm4(uint32_t &r0, uint32_t &r1, uint32_t &r2,
                                      uint32_t &r3, uint32_t addr) {
    asm volatile("ldmatrix.sync.aligned.m8n8.x4.shared.b16 {%0,%1,%2,%3}, [%4];"
                 : "=r"(r0), "=r"(r1), "=r"(r2), "=r"(r3) : "r"(addr));
}
__device__ __forceinline__ void mma16816(float c[4], const uint32_t a[4],
                                         uint32_t b0, uint32_t b1) {
    asm volatile(
        "mma.sync.aligned.m16n8k16.row.col.f32.bf16.bf16.f32 "
        "{%0,%1,%2,%3}, {%4,%5,%6,%7}, {%8,%9}, {%0,%1,%2,%3};"
        : "+f"(c[0]), "+f"(c[1]), "+f"(c[2]), "+f"(c[3])
        : "r"(a[0]), "r"(a[1]), "r"(a[2]), "r"(a[3]), "r"(b0), "r"(b1));
}
__device__ __forceinline__ void cpasync16(uint32_t saddr, const void* g) {
    asm volatile("cp.async.cg.shared.global [%0], [%1], 16;" :: "r"(saddr), "l"(g));
}
#define CP_COMMIT() asm volatile("cp.async.commit_group;" ::: "memory")
#define CP_WAIT0()  asm volatile("cp.async.wait_group 0;" ::: "memory")

__device__ __forceinline__ void cvt_split(float x, uint32_t &h, uint32_t &l) {
    __nv_bfloat16 bh = __float2bfloat16_rn(x);
    float r = x - __bfloat162float(bh);
    __nv_bfloat16 bl = __float2bfloat16_rn(r);
    h = (uint32_t)__bfloat16_as_ushort(bh);
    l = (uint32_t)__bfloat16_as_ushort(bl);
}

// ---------------- scratch (device globals; no runtime allocation) -----------
__device__ float g_proj[4*BT_*D_];     // q | k | v | s
#define GQ (g_proj)
#define GK (g_proj + 1*BT_*D_)
#define GV (g_proj + 2*BT_*D_)
#define GS (g_proj + 3*BT_*D_)
__device__ float g_g [BT_*256];
__device__ float g_st1[8*32*256*64];
__device__ float g_st2[8*32*64*256];
__device__ float g_o [BT_*D_];
__device__ __nv_bfloat16 g_hh[BT_*D_];
__device__ __nv_bfloat16 g_hl[BT_*D_];
__device__ __nv_bfloat16 g_wh[6*D_*D_];   // Wq Wk Wv Ws | Wo | Wg(partial)
__device__ __nv_bfloat16 g_wl[6*D_*D_];

// ---------------- weight split kernels ---------------------------------------
__global__ void split_kernel(const float* __restrict__ x,
                             __nv_bfloat16* __restrict__ hi,
                             __nv_bfloat16* __restrict__ lo) {
    int i = blockIdx.x*256 + threadIdx.x;
    float4 v = ((const float4*)x)[i];
    uint32_t h0,l0,h1,l1,h2,l2,h3,l3;
    cvt_split(v.x, h0, l0); cvt_split(v.y, h1, l1);
    cvt_split(v.z, h2, l2); cvt_split(v.w, h3, l3);
    ((uint2*)hi)[i] = make_uint2(h0 | (h1<<16), h2 | (h3<<16));
    ((uint2*)lo)[i] = make_uint2(l0 | (l1<<16), l2 | (l3<<16));
}
__global__ void split4_kernel(const float* __restrict__ w0, const float* __restrict__ w1,
                              const float* __restrict__ w2, const float* __restrict__ w3,
                              __nv_bfloat16* __restrict__ hi,
                              __nv_bfloat16* __restrict__ lo) {
    int w = blockIdx.x >> 10;
    int i = ((blockIdx.x & 1023) << 8) + threadIdx.x;
    const float* src = (w == 0) ? w0 : (w == 1) ? w1 : (w == 2) ? w2 : w3;
    float4 v = ((const float4*)src)[i];
    uint32_t h0,l0,h1,l1,h2,l2,h3,l3;
    cvt_split(v.x, h0, l0); cvt_split(v.y, h1, l1);
    cvt_split(v.z, h2, l2); cvt_split(v.w, h3, l3);
    size_t o = (size_t)w*262144 + i;
    ((uint2*)hi)[o] = make_uint2(h0 | (h1<<16), h2 | (h3<<16));
    ((uint2*)lo)[o] = make_uint2(l0 | (l1<<16), l2 | (l3<<16));
}

// ---------------- RMSNorm -> split bf16 --------------------------------------
__global__ void rms_kernel(const float* __restrict__ x, const float* __restrict__ w,
                           __nv_bfloat16* __restrict__ ohi,
                           __nv_bfloat16* __restrict__ olo) {
    __shared__ float red[8];
    int row = blockIdx.x;
    const float* xr = x + (size_t)row * D_;
    float v[4]; float ss = 0.f;
#pragma unroll
    for (int i = 0; i < 4; i++) { float t = xr[threadIdx.x + i*256]; v[i] = t; ss += t*t; }
#pragma unroll
    for (int o = 16; o; o >>= 1) ss += __shfl_xor_sync(0xffffffffu, ss, o);
    if ((threadIdx.x & 31) == 0) red[threadIdx.x >> 5] = ss;
    __syncthreads();
    float tot = 0.f;
#pragma unroll
    for (int i = 0; i < 8; i++) tot += red[i];
    float inv = rsqrtf(tot * (1.0f/1024.0f) + 1e-5f);
#pragma unroll
    for (int i = 0; i < 4; i++) {
        int c = threadIdx.x + i*256;
        float y = v[i] * inv * w[c];
        uint32_t h, l; cvt_split(y, h, l);
        ohi[(size_t)row*D_ + c] = __ushort_as_bfloat16((unsigned short)h);
        olo[(size_t)row*D_ + c] = __ushort_as_bfloat16((unsigned short)l);
    }
}

// ---------------- SiLU + RMSNorm -> split bf16 -------------------------------
__global__ void silu_rms_kernel(const float* __restrict__ x, const float* __restrict__ w,
                                __nv_bfloat16* __restrict__ ohi,
                                __nv_bfloat16* __restrict__ olo) {
    __shared__ float red[8];
    int row = blockIdx.x;
    const float* xr = x + (size_t)row * D_;
    float y[4]; float ss = 0.f;
#pragma unroll
    for (int i = 0; i < 4; i++) {
        float t = xr[threadIdx.x + i*256];
        float yy = t / (1.0f + __expf(-t));
        y[i] = yy; ss += yy*yy;
    }
#pragma unroll
    for (int o = 16; o; o >>= 1) ss += __shfl_xor_sync(0xffffffffu, ss, o);
    if ((threadIdx.x & 31) == 0) red[threadIdx.x >> 5] = ss;
    __syncthreads();
    float tot = 0.f;
#pragma unroll
    for (int i = 0; i < 8; i++) tot += red[i];
    float inv = rsqrtf(tot * (1.0f/1024.0f) + 1e-5f);
#pragma unroll
    for (int i = 0; i < 4; i++) {
        int c = threadIdx.x + i*256;
        float yv = y[i] * inv * w[c];
        uint32_t h, l; cvt_split(yv, h, l);
        ohi[(size_t)row*D_ + c] = __ushort_as_bfloat16((unsigned short)h);
        olo[(size_t)row*D_ + c] = __ushort_as_bfloat16((unsigned short)l);
    }
}

// ---------------- gate softmax over 256 --------------------------------------
__global__ void softmax_g_kernel(float* __restrict__ gm) {
    __shared__ float red[8];
    int row = blockIdx.x;
    float v = gm[(size_t)row*256 + threadIdx.x];
    float m = v;
#pragma unroll
    for (int o = 16; o; o >>= 1) m = fmaxf(m, __shfl_xor_sync(0xffffffffu, m, o));
    if ((threadIdx.x & 31) == 0) red[threadIdx.x >> 5] = m;
    __syncthreads();
    float mm = red[0];
#pragma unroll
    for (int i = 1; i < 8; i++) mm = fmaxf(mm, red[i]);
    float e = __expf(v - mm);
    float s = e;
#pragma unroll
    for (int o = 16; o; o >>= 1) s += __shfl_xor_sync(0xffffffffu, s, o);
    __syncthreads();
    if ((threadIdx.x & 31) == 0) red[threadIdx.x >> 5] = s;
    __syncthreads();
    float tot = 0.f;
#pragma unroll
    for (int i = 0; i < 8; i++) tot += red[i];
    gm[(size_t)row*256 + threadIdx.x] = e / tot;
}

// ---------------- HMMA split-bf16 GEMM: C[M,N] = A[M,K] @ W[N,K]^T -----------
#define GM_STRIDE 80
#define GM_ARR    10240
#define GM_STAGE  40960
#define GM_SMEM   81920

__global__ void __launch_bounds__(256, 2) gemm_mma(const __nv_bfloat16* __restrict__ Ah,
                                                   const __nv_bfloat16* __restrict__ Al,
                                                   const __nv_bfloat16* __restrict__ Bh,
                                                   const __nv_bfloat16* __restrict__ Bl,
                                                   float* __restrict__ Cb, int N,
                                                   size_t wstride, size_t cstride) {
    extern __shared__ char smem[];
    uint32_t sb = smem_u32(smem);
    int tid = threadIdx.x;
    int lane = tid & 31, wid = tid >> 5;
    int wm = wid >> 2, wn = wid & 3;
    int m0 = blockIdx.y * 128, n0 = blockIdx.x * 128;
    size_t zo = (size_t)blockIdx.z * wstride;
    float* C = Cb + (size_t)blockIdx.z * cstride;

    const __nv_bfloat16* srcs[4];
    srcs[0] = Ah + (size_t)m0*1024;
    srcs[1] = Al + (size_t)m0*1024;
    srcs[2] = Bh + zo + (size_t)n0*1024;
    srcs[3] = Bl + zo + (size_t)n0*1024;

    float acc[4][4][4];
#pragma unroll
    for (int i = 0; i < 4; i++)
#pragma unroll
        for (int j = 0; j < 4; j++)
#pragma unroll
            for (int e = 0; e < 4; e++) acc[i][j][e] = 0.f;

    int row_l = tid >> 2, c8 = tid & 3;

    {   // prologue: stage 0
        uint32_t base = sb;
#pragma unroll
        for (int arr = 0; arr < 4; arr++)
#pragma unroll
            for (int l = 0; l < 2; l++) {
                int row = row_l + l*64;
                cpasync16(base + arr*GM_ARR + row*GM_STRIDE + c8*16,
                          srcs[arr] + (size_t)row*1024 + c8*8);
            }
        CP_COMMIT();
    }

    for (int s = 0; s < 32; s++) {
        CP_WAIT0();
        __syncthreads();
        if (s + 1 < 32) {
            uint32_t base = sb + ((s+1) & 1)*GM_STAGE;
            int k0 = (s+1)*32;
#pragma unroll
            for (int arr = 0; arr < 4; arr++)
#pragma unroll
                for (int l = 0; l < 2; l++) {
                    int row = row_l + l*64;
                    cpasync16(base + arr*GM_ARR + row*GM_STRIDE + c8*16,
                              srcs[arr] + (size_t)row*1024 + k0 + c8*8);
                }
            CP_COMMIT();
        }
        uint32_t stb = sb + (s & 1)*GM_STAGE;
#pragma unroll
        for (int kk = 0; kk < 2; kk++) {
            uint32_t bh[4][2], bl[4][2];
            int rowB = wn*32 + ((lane >> 4) & 1)*8 + (lane & 7);
            int colB = kk*32 + ((lane >> 3) & 1)*16;
#pragma unroll
            for (int np = 0; np < 2; np++) {
                uint32_t rb = (rowB + np*16)*GM_STRIDE + colB;
                uint32_t r0,r1,r2,r3;
                ldsm4(r0, r1, r2, r3, stb + 2*GM_ARR + rb);
                bh[np*2][0] = r0; bh[np*2][1] = r1; bh[np*2+1][0] = r2; bh[np*2+1][1] = r3;
                ldsm4(r0, r1, r2, r3, stb + 3*GM_ARR + rb);
                bl[np*2][0] = r0; bl[np*2][1] = r1; bl[np*2+1][0] = r2; bl[np*2+1][1] = r3;
            }
            int colA = kk*32 + ((lane >> 4) & 1)*16;
            uint32_t ah[2][4], al[2][4];
            {
                uint32_t ra = (wm*64 + (lane & 15))*GM_STRIDE + colA;
                ldsm4(ah[0][0], ah[0][1], ah[0][2], ah[0][3], stb + ra);
                ldsm4(al[0][0], al[0][1], al[0][2], al[0][3], stb + GM_ARR + ra);
            }
#pragma unroll
            for (int mi = 0; mi < 4; mi++) {
                int cur = mi & 1;
                if (mi < 3) {
                    uint32_t ra = (wm*64 + (mi+1)*16 + (lane & 15))*GM_STRIDE + colA;
                    ldsm4(ah[cur^1][0], ah[cur^1][1], ah[cur^1][2], ah[cur^1][3], stb + ra);
                    ldsm4(al[cur^1][0], al[cur^1][1], al[cur^1][2], al[cur^1][3],
                          stb + GM_ARR + ra);
                }
#pragma unroll
                for (int nj = 0; nj < 4; nj++) {
                    mma16816(acc[mi][nj], ah[cur], bh[nj][0], bh[nj][1]);
                    mma16816(acc[mi][nj], ah[cur], bl[nj][0], bl[nj][1]);
                    mma16816(acc[mi][nj], al[cur], bh[nj][0], bh[nj][1]);
                }
            }
        }
        __syncthreads();
    }
#pragma unroll
    for (int mi = 0; mi < 4; mi++) {
        int r = m0 + wm*64 + mi*16 + (lane >> 2);
#pragma unroll
        for (int nj = 0; nj < 4; nj++) {
            int cc = n0 + wn*32 + nj*8 + (lane & 3)*2;
            *(float2*)(C + (size_t)r*N + cc)     = make_float2(acc[mi][nj][0], acc[mi][nj][1]);
            *(float2*)(C + (size_t)(r+8)*N + cc) = make_float2(acc[mi][nj][2], acc[mi][nj][3]);
        }
    }
}

// ---------------- per-chunk outer products (state sums) ----------------------
__global__ void __launch_bounds__(256) chunk_outer_kernel() {
    __shared__ float gsm[64*68];
    int id = blockIdx.x;
    int which = id >> 8;
    int sub = id & 255;
    int bh = sub >> 5, c = sub & 31;
    int b = bh >> 2, h = bh & 3;
    int tid = threadIdx.x;
    const float* gsrc = g_g + (size_t)(b*T_ + c*64)*256 + h*64;
#pragma unroll
    for (int e = 0; e < 16; e++) {
        int idx = tid + e*256; int u = idx >> 6, j = idx & 63;
        gsm[u*68 + j] = gsrc[(size_t)u*256 + j];
    }
    __syncthreads();
    ull acc2[32];
#pragma unroll
    for (int j = 0; j < 32; j++) acc2[j] = 0ull;
    const float* src = (which == 0)
        ? (GS + (size_t)(b*T_ + c*64)*D_ + h*256 + tid)
        : (GV + (size_t)(b*T_ + c*64)*D_ + h*256 + tid);
    for (int u = 0; u < 64; u++) {
        float sv = src[(size_t)u*D_];
        ull sd = pk2(sv, sv);
#pragma unroll
        for (int j4 = 0; j4 < 16; j4++) {
            float4 gg = *(const float4*)(gsm + u*68 + j4*4);
            ffma2(acc2[j4*2+0], sd, pk2(gg.x, gg.y));
            ffma2(acc2[j4*2+1], sd, pk2(gg.z, gg.w));
        }
    }
    if (which == 0) {
        float* dst = g_st1 + ((size_t)(bh*32 + c)*256 + tid)*64;
#pragma unroll
        for (int j2 = 0; j2 < 32; j2++) {
            float lo, hi; upk2(acc2[j2], lo, hi);
            *(float2*)(dst + j2*2) = make_float2(lo, hi);
        }
    } else {
        float* dst = g_st2 + (size_t)(bh*32 + c)*16384 + tid;
#pragma unroll
        for (int j2 = 0; j2 < 32; j2++) {
            float lo, hi; upk2(acc2[j2], lo, hi);
            dst[(size_t)(j2*2)*256]   = lo;
            dst[(size_t)(j2*2+1)*256] = hi;
        }
    }
}

// ---------------- exclusive scan over 32 chunks ------------------------------
__global__ void scan_kernel() {
    int gb = blockIdx.x;
    int which = gb >> 9;
    int sub = gb & 511;
    int bh = sub >> 6;
    int e = (sub & 63)*256 + threadIdx.x;
    float* base = which ? g_st2 : g_st1;
    float run = 0.f;
    for (int c = 0; c < 32; c++) {
        size_t idx = ((size_t)(bh*32 + c) << 14) + e;
        float t = base[idx]; base[idx] = run; run += t;
    }
}

// ---------------- attention helpers (512-thread variants) --------------------
__device__ __forceinline__ void ldT64w(float* dst, const float* src, int lds_, int tid) {
#pragma unroll
    for (int e = 0; e < 8; e++) {
        int idx = tid + e*512; int r = idx >> 6, kk = idx & 63;
        dst[kk*68 + r] = src[(size_t)r*lds_ + kk];
    }
}
__device__ __forceinline__ void ldg8(float r[8], const float* src, int lds_, int tid) {
#pragma unroll
    for (int e = 0; e < 8; e++) {
        int idx = tid + e*512;
        r[e] = src[(size_t)(idx >> 6)*lds_ + (idx & 63)];
    }
}
__device__ __forceinline__ void sts8T(float* dst, const float r[8], int tid) {
#pragma unroll
    for (int e = 0; e < 8; e++) {
        int idx = tid + e*512;
        dst[(idx & 63)*68 + (idx >> 6)] = r[e];   // transposed store
    }
}
__device__ __forceinline__ void sts8D(float* dst, const float r[8], int tid) {
#pragma unroll
    for (int e = 0; e < 8; e++) {
        int idx = tid + e*512;
        dst[(idx >> 6)*68 + (idx & 63)] = r[e];   // direct store
    }
}
__device__ __forceinline__ void ldD64w(float* dst, const float* src, int lds_, int tid) {
#pragma unroll
    for (int e = 0; e < 8; e++) {
        int idx = tid + e*512; int k = idx >> 6, j = idx & 63;
        dst[k*68 + j] = src[(size_t)k*lds_ + j];
    }
}
__device__ __forceinline__ void ldVw(float* vsm, const float* src, int lds_, int tid) {
#pragma unroll
    for (int e = 0; e < 8; e++) {
        int idx = tid + e*512; int u = idx >> 6, c4 = idx & 63;
        *(float4*)(vsm + u*264 + c4*4) = *(const float4*)(src + (size_t)u*lds_ + c4*4);
    }
}
// acc2[i][jp]: rows ty*2+i, col pairs tx*4 + jp*2
__device__ __forceinline__ void gemm8(ull acc2[2][2], const float* A, const float* Bq,
                                      int nk, int ty, int tx) {
    for (int k = 0; k < nk; k++) {
        float2 a2 = *(const float2*)(A  + k*68 + ty*2);
        float4 b4 = *(const float4*)(Bq + k*68 + tx*4);
        ull bp0 = pk2(b4.x, b4.y), bp1 = pk2(b4.z, b4.w);
        {
            ull ad = pk2(a2.x, a2.x);
            ffma2(acc2[0][0], ad, bp0);
            ffma2(acc2[0][1], ad, bp1);
        }
        {
            ull ad = pk2(a2.y, a2.y);
            ffma2(acc2[1][0], ad, bp0);
            ffma2(acc2[1][1], ad, bp1);
        }
    }
}
__device__ __forceinline__ void unpk8(float dst[2][4], const ull a2[2][2]) {
#pragma unroll
    for (int i = 0; i < 2; i++) {
        upk2(a2[i][0], dst[i][0], dst[i][1]);
        upk2(a2[i][1], dst[i][2], dst[i][3]);
    }
}
// o2[i][j][p]: rows ty*2+i, cols tx*4 + j*64 + p*2
__device__ __forceinline__ void pv_acc8(ull o2[2][4][2], const float* P, const float* V,
                                        int ty, int tx) {
    for (int u = 0; u < 64; u++) {
        float2 p2 = *(const float2*)(P + u*68 + ty*2);
        ull pd0 = pk2(p2.x, p2.x), pd1 = pk2(p2.y, p2.y);
#pragma unroll
        for (int j = 0; j < 4; j++) {
            float4 v4 = *(const float4*)(V + u*264 + tx*4 + j*64);
            ull vp0 = pk2(v4.x, v4.y), vp1 = pk2(v4.z, v4.w);
            ffma2(o2[0][j][0], pd0, vp0);
            ffma2(o2[0][j][1], pd0, vp1);
            ffma2(o2[1][j][0], pd1, vp0);
            ffma2(o2[1][j][1], pd1, vp1);
        }
    }
}
// 8 segments of 8 u-entries per row; reduce over lanes xor 1,2,4
__device__ __forceinline__ float rowmax8(const float* arr, int r, int seg) {
    float v = -3.4e38f;
#pragma unroll
    for (int uu = 0; uu < 8; uu++) v = fmaxf(v, arr[(seg*8+uu)*68 + r]);
    v = fmaxf(v, __shfl_xor_sync(0xffffffffu, v, 1));
    v = fmaxf(v, __shfl_xor_sync(0xffffffffu, v, 2));
    v = fmaxf(v, __shfl_xor_sync(0xffffffffu, v, 4));
    return v;
}
__device__ __forceinline__ float rowsum8(const float* arr, int r, int seg) {
    float v = 0.f;
#pragma unroll
    for (int uu = 0; uu < 8; uu++) v += arr[(seg*8+uu)*68 + r];
    v += __shfl_xor_sync(0xffffffffu, v, 1);
    v += __shfl_xor_sync(0xffffffffu, v, 2);
    v += __shfl_xor_sync(0xffffffffu, v, 4);
    return v;
}

// smem: qsT 17408 | Bs0 4352 | Bs1 4352 | psh 4352 | sst 4352 | vsm 16896 | 192
#define SMEM_ATTN (51904*4)

// ---------------- fused attention: grid 256 (bh*32 + tile), 512 threads ------
__global__ void __launch_bounds__(512) attn_kernel() {
    extern __shared__ float sm[];
    float* qsT  = sm;
    float* Bs   = qsT + 256*68;          // double buffer: Bs, Bs+4352
    float* psh  = Bs  + 2*64*68;
    float* sst  = psh + 64*68;
    float* vsm  = sst + 64*68;
    float* mrow = vsm + 64*264;
    float* zrow = mrow + 64;
    float* frow = zrow + 64;

    int tid = threadIdx.x;
    int tx = tid & 15, ty = tid >> 4;     // ty 0..31 (2 rows), tx 0..15 (4 cols)
    int tile = blockIdx.x & 31, bh = blockIdx.x >> 5;
    int b = bh >> 2, h = bh & 3;
    int t0 = tile*64;
    float slope = exp2f(-2.0f*(float)h);
    int r8 = tid >> 3, seg = tid & 7;     // 64 rows x 8 segments

    const float* qbase = GQ + (size_t)(b*T_ + t0)*D_ + h*256;
    const float* sbase = GS + (size_t)(b*T_ + t0)*D_ + h*256;
    const float* gbase = g_g + (size_t)(b*T_ + t0)*256 + h*64;
    const float* kbase = GK + (size_t)(b*T_)*D_ + h*256;
    const float* vbase = GV + (size_t)(b*T_)*D_ + h*256;
    const float* st1   = g_st1 + (size_t)(bh*32 + tile)*16384;
    const float* st2   = g_st2 + (size_t)(bh*32 + tile)*16384;

    for (int ks = 0; ks < 4; ks++) ldT64w(qsT + ks*64*68, qbase + ks*64, D_, tid);

    ull acc2[2][2];
    float acc[2][4];
    // ---- A_intra = mask(q @ s^T), pipelined s loads (transposed stores) ----
#pragma unroll
    for (int i = 0; i < 2; i++) { acc2[i][0] = 0ull; acc2[i][1] = 0ull; }
    {
        float bufr[2][8];
        ldg8(bufr[0], sbase, D_, tid);
#pragma unroll
        for (int ks = 0; ks < 4; ks++) {
            if (ks < 3) ldg8(bufr[(ks+1)&1], sbase + (ks+1)*64, D_, tid);
            sts8T(Bs + (ks&1)*4352, bufr[ks&1], tid);
            __syncthreads();
            gemm8(acc2, qsT + ks*64*68, Bs + (ks&1)*4352, 64, ty, tx);
        }
    }
    unpk8(acc, acc2);
    __syncthreads();
#pragma unroll
    for (int i = 0; i < 2; i++)
#pragma unroll
        for (int j = 0; j < 4; j++) {
            int r = ty*2+i, uu = tx*4+j;
            psh[uu*68 + r] = (uu <= r) ? acc[i][j] : 0.f;
        }
    __syncthreads();
    // ---- sc_state = A_intra @ g + q @ St1prefix ----
#pragma unroll
    for (int i = 0; i < 2; i++) { acc2[i][0] = 0ull; acc2[i][1] = 0ull; }
    ldD64w(Bs, gbase, 256, tid);
    __syncthreads();
    gemm8(acc2, psh, Bs, 64, ty, tx);
    {
        float bufr[2][8];
        ldg8(bufr[0], st1, 64, tid);
#pragma unroll
        for (int ks = 0; ks < 4; ks++) {
            if (ks < 3) ldg8(bufr[(ks+1)&1], st1 + (ks+1)*64*64, 64, tid);
            __syncthreads();
            sts8D(Bs + (ks&1)*4352, bufr[ks&1], tid);   // direct store
            __syncthreads();
            gemm8(acc2, qsT + ks*64*68, Bs + (ks&1)*4352, 64, ty, tx);
        }
    }
    unpk8(acc, acc2);
    __syncthreads();
#pragma unroll
    for (int i = 0; i < 2; i++)
#pragma unroll
        for (int j = 0; j < 4; j++)
            sst[(tx*4+j)*68 + ty*2+i] = acc[i][j];
    __syncthreads();
    {
        float mx = rowmax8(sst, r8, seg);
        if (seg == 0) { mrow[r8] = mx; zrow[r8] = 0.f; }
    }
    ull o2[2][4][2];
#pragma unroll
    for (int i = 0; i < 2; i++)
#pragma unroll
        for (int j = 0; j < 4; j++) { o2[i][j][0] = 0ull; o2[i][j][1] = 0ull; }
    __syncthreads();

    // ---- sliding-window chunks, pipelined K loads ----
    for (int ci = 0; ci < 9; ci++) {
        int u0 = t0 - 512 + ci*64;
        if (u0 < 0) continue;
#pragma unroll
        for (int i = 0; i < 2; i++) { acc2[i][0] = 0ull; acc2[i][1] = 0ull; }
        {
            const float* kc = kbase + (size_t)u0*D_;
            float bufr[2][8];
            ldg8(bufr[0], kc, D_, tid);
#pragma unroll
            for (int ks = 0; ks < 4; ks++) {
                if (ks < 3) ldg8(bufr[(ks+1)&1], kc + (ks+1)*64, D_, tid);
                sts8T(Bs + (ks&1)*4352, bufr[ks&1], tid);
                __syncthreads();
                gemm8(acc2, qsT + ks*64*68, Bs + (ks&1)*4352, 64, ty, tx);
            }
        }
        unpk8(acc, acc2);
        __syncthreads();
#pragma unroll
        for (int i = 0; i < 2; i++)
#pragma unroll
            for (int j = 0; j < 4; j++) {
                int r = ty*2+i, uu = tx*4+j;
                int d = t0 + r - u0 - uu;
                psh[uu*68 + r] = (d >= 0 && d < 512) ? acc[i][j] - slope*(float)d : -1e30f;
            }
        __syncthreads();
        {
            float cm = rowmax8(psh, r8, seg);
            if (seg == 0) {
                float mo = mrow[r8], mn = fmaxf(mo, cm);
                frow[r8] = __expf(mo - mn); mrow[r8] = mn;
            }
        }
        __syncthreads();
#pragma unroll
        for (int e = 0; e < 8; e++) {
            int idx = tid + e*512; int uu = idx >> 6, r = idx & 63;
            psh[uu*68 + r] = __expf(psh[uu*68 + r] - mrow[r]);
        }
        __syncthreads();
        {
            float cz = rowsum8(psh, r8, seg);
            if (seg == 0) zrow[r8] = zrow[r8]*frow[r8] + cz;
        }
        ldVw(vsm, vbase + (size_t)u0*D_, D_, tid);
        __syncthreads();
#pragma unroll
        for (int i = 0; i < 2; i++) {
            float f = frow[ty*2 + i];
            ull fd = pk2(f, f);
#pragma unroll
            for (int j = 0; j < 4; j++) {
                fmul2(o2[i][j][0], fd); fmul2(o2[i][j][1], fd);
            }
        }
        pv_acc8(o2, psh, vsm, ty, tx);
    }
    __syncthreads();
    // ---- fold in state scores, finalize softmax ----
#pragma unroll
    for (int e = 0; e < 8; e++) {
        int idx = tid + e*512; int j = idx >> 6, r = idx & 63;
        sst[j*68 + r] = __expf(sst[j*68 + r] - mrow[r]);
    }
    __syncthreads();
    {
        float zs = rowsum8(sst, r8, seg);
        if (seg == 0) frow[r8] = 1.0f / (zrow[r8] + zs);
    }
    __syncthreads();
#pragma unroll
    for (int e = 0; e < 8; e++) {
        int idx = tid + e*512; int j = idx >> 6, r = idx & 63;
        sst[j*68 + r] *= frow[r];
    }
#pragma unroll
    for (int i = 0; i < 2; i++) {
        float fi = frow[ty*2 + i];
        ull fd = pk2(fi, fi);
#pragma unroll
        for (int j = 0; j < 4; j++) {
            fmul2(o2[i][j][0], fd); fmul2(o2[i][j][1], fd);
        }
    }
    ldVw(vsm, st2, 256, tid);
    ldT64w(Bs, gbase, 256, tid);
    __syncthreads();
    pv_acc8(o2, sst, vsm, ty, tx);
#pragma unroll
    for (int i = 0; i < 2; i++) { acc2[i][0] = 0ull; acc2[i][1] = 0ull; }
    gemm8(acc2, sst, Bs, 64, ty, tx);
    unpk8(acc, acc2);
    __syncthreads();
#pragma unroll
    for (int i = 0; i < 2; i++)
#pragma unroll
        for (int j = 0; j < 4; j++) {
            int r = ty*2+i, uu = tx*4+j;
            psh[uu*68 + r] = (uu <= r) ? acc[i][j] : 0.f;
        }
    ldVw(vsm, vbase + (size_t)t0*D_, D_, tid);
    __syncthreads();
    pv_acc8(o2, psh, vsm, ty, tx);
    float* obase = g_o + (size_t)(b*T_ + t0)*D_ + h*256;
#pragma unroll
    for (int i = 0; i < 2; i++) {
        float* dst = obase + (size_t)(ty*2+i)*D_;
#pragma unroll
        for (int j = 0; j < 4; j++) {
            float x0,x1,x2,x3;
            upk2(o2[i][j][0], x0, x1);
            upk2(o2[i][j][1], x2, x3);
            *(float4*)(dst + tx*4 + j*64) = make_float4(x0,x1,x2,x3);
        }
    }
}

// ---------------- launch -----------------------------------------------------
extern "C" void kernel_launch(void* const* d_in, const int* in_sizes, int n_in,
                              void* d_out, int out_size) {
    const float* hidden = (const float*)d_in[0];
    const float* wnorm  = (const float*)d_in[1];
    const float* Wq = (const float*)d_in[2];
    const float* Wk = (const float*)d_in[3];
    const float* Wv = (const float*)d_in[4];
    const float* Ws = (const float*)d_in[5];
    const float* Wg = (const float*)d_in[6];
    const float* Wo = (const float*)d_in[7];
    float* out = (float*)d_out;

    float *pproj, *pg, *po;
    __nv_bfloat16 *phh, *phl, *pwh, *pwl;
    cudaGetSymbolAddress((void**)&pproj, g_proj);
    cudaGetSymbolAddress((void**)&pg, g_g);
    cudaGetSymbolAddress((void**)&po, g_o);
    cudaGetSymbolAddress((void**)&phh, g_hh);
    cudaGetSymbolAddress((void**)&phl, g_hl);
    cudaGetSymbolAddress((void**)&pwh, g_wh);
    cudaGetSymbolAddress((void**)&pwl, g_wl);

    cudaFuncSetAttribute(attn_kernel, cudaFuncAttributeMaxDynamicSharedMemorySize, SMEM_ATTN);
    cudaFuncSetAttribute(gemm_mma, cudaFuncAttributeMaxDynamicSharedMemorySize, GM_SMEM);

    const size_t WSLOT = (size_t)D_*D_;       // 1048576 elems
    const size_t CSLOT = (size_t)BT_*D_;      // 4194304 elems

    rms_kernel<<<BT_, 256>>>(hidden, wnorm, phh, phl);                            // 1
    split4_kernel<<<4096, 256>>>(Wq, Wk, Wv, Ws, pwh, pwl);                       // 2
    split_kernel<<<1024, 256>>>(Wo, pwh + 4*WSLOT, pwl + 4*WSLOT);                // 3
    gemm_mma<<<dim3(8,32,4), 256, GM_SMEM>>>(phh, phl, pwh, pwl,                  // 4
                                             pproj, 1024, WSLOT, CSLOT);
    split_kernel<<<256, 256>>>(Wg, pwh + 5*WSLOT, pwl + 5*WSLOT);                 // 5
    gemm_mma<<<dim3(2,32,1), 256, GM_SMEM>>>(phh, phl, pwh + 5*WSLOT, pwl + 5*WSLOT, // 6
                                             pg, 256, 0, 0);
    softmax_g_kernel<<<BT_, 256>>>(pg);
    chunk_outer_kernel<<<512, 256>>>();
    scan_kernel<<<1024, 256>>>();
    attn_kernel<<<256, 512, SMEM_ATTN>>>();
    silu_rms_kernel<<<BT_, 256>>>(po, wnorm, phh, phl);
    gemm_mma<<<dim3(8,32,1), 256, GM_SMEM>>>(phh, phl, pwh + 4*WSLOT, pwl + 4*WSLOT,
                                             out, 1024, 0, 0);
}

// round 17
// speedup vs baseline: 1.1763x; 1.1763x over previous
#include <cuda_runtime.h>
#include <cuda_bf16.h>
#include <math.h>
#include <stdint.h>

#define B_  2
#define T_  2048
#define D_  1024
#define H_  4
#define BT_ 4096

typedef unsigned long long ull;

// ---- packed f32x2 helpers ---------------------------------------------------
__device__ __forceinline__ ull pk2(float lo, float hi) {
    ull r; asm("mov.b64 %0, {%1, %2};" : "=l"(r) : "f"(lo), "f"(hi)); return r;
}
__device__ __forceinline__ void ffma2(ull &c, ull a, ull b) {
    asm("fma.rn.f32x2 %0, %1, %2, %0;" : "+l"(c) : "l"(a), "l"(b));
}
__device__ __forceinline__ void fmul2(ull &c, ull f) {
    asm("mul.rn.f32x2 %0, %0, %1;" : "+l"(c) : "l"(f));
}
__device__ __forceinline__ void upk2(ull v, float &lo, float &hi) {
    asm("mov.b64 {%0, %1}, %2;" : "=f"(lo), "=f"(hi) : "l"(v));
}

// ---- mma.sync / ldmatrix / cp.async helpers (arch-portable sm_80+) ----------
__device__ __forceinline__ uint32_t smem_u32(const void* p) {
    uint32_t a;
    asm("{ .reg .u64 t; cvta.to.shared.u64 t, %1; cvt.u32.u64 %0, t; }"
        : "=r"(a) : "l"(p));
    return a;
}
__device__ __forceinline__ void ldsm4(uint32_t &r0, uint32_t &r1, uint32_t &r2,
                                      uint32_t &r3, uint32_t addr) {
    asm volatile("ldmatrix.sync.aligned.m8n8.x4.shared.b16 {%0,%1,%2,%3}, [%4];"
                 : "=r"(r0), "=r"(r1), "=r"(r2), "=r"(r3) : "r"(addr));
}
__device__ __forceinline__ void mma16816(float c[4], const uint32_t a[4],
                                         uint32_t b0, uint32_t b1) {
    asm volatile(
        "mma.sync.aligned.m16n8k16.row.col.f32.bf16.bf16.f32 "
        "{%0,%1,%2,%3}, {%4,%5,%6,%7}, {%8,%9}, {%0,%1,%2,%3};"
        : "+f"(c[0]), "+f"(c[1]), "+f"(c[2]), "+f"(c[3])
        : "r"(a[0]), "r"(a[1]), "r"(a[2]), "r"(a[3]), "r"(b0), "r"(b1));
}
__device__ __forceinline__ void cpasync16(uint32_t saddr, const void* g) {
    asm volatile("cp.async.cg.shared.global [%0], [%1], 16;" :: "r"(saddr), "l"(g));
}
#define CP_COMMIT() asm volatile("cp.async.commit_group;" ::: "memory")
#define CP_WAIT0()  asm volatile("cp.async.wait_group 0;" ::: "memory")

__device__ __forceinline__ void cvt_split(float x, uint32_t &h, uint32_t &l) {
    __nv_bfloat16 bh = __float2bfloat16_rn(x);
    float r = x - __bfloat162float(bh);
    __nv_bfloat16 bl = __float2bfloat16_rn(r);
    h = (uint32_t)__bfloat16_as_ushort(bh);
    l = (uint32_t)__bfloat16_as_ushort(bl);
}

// ---------------- scratch (device globals; no runtime allocation) -----------
__device__ float g_proj[4*BT_*D_];     // q | k | v | s
#define GQ (g_proj)
#define GK (g_proj + 1*BT_*D_)
#define GV (g_proj + 2*BT_*D_)
#define GS (g_proj + 3*BT_*D_)
__device__ float g_g [BT_*256];
__device__ float g_st1[8*32*256*64];
__device__ float g_st2[8*32*64*256];
__device__ float g_o [BT_*D_];
__device__ __nv_bfloat16 g_hh[BT_*D_];
__device__ __nv_bfloat16 g_hl[BT_*D_];
__device__ __nv_bfloat16 g_wh[6*D_*D_];   // Wq Wk Wv Ws | Wg | Wo
__device__ __nv_bfloat16 g_wl[6*D_*D_];

// ---------------- weight split kernels ---------------------------------------
__global__ void split_kernel(const float* __restrict__ x,
                             __nv_bfloat16* __restrict__ hi,
                             __nv_bfloat16* __restrict__ lo) {
    int i = blockIdx.x*256 + threadIdx.x;
    float4 v = ((const float4*)x)[i];
    uint32_t h0,l0,h1,l1,h2,l2,h3,l3;
    cvt_split(v.x, h0, l0); cvt_split(v.y, h1, l1);
    cvt_split(v.z, h2, l2); cvt_split(v.w, h3, l3);
    ((uint2*)hi)[i] = make_uint2(h0 | (h1<<16), h2 | (h3<<16));
    ((uint2*)lo)[i] = make_uint2(l0 | (l1<<16), l2 | (l3<<16));
}
__global__ void split4_kernel(const float* __restrict__ w0, const float* __restrict__ w1,
                              const float* __restrict__ w2, const float* __restrict__ w3,
                              __nv_bfloat16* __restrict__ hi,
                              __nv_bfloat16* __restrict__ lo) {
    int w = blockIdx.x >> 10;
    int i = ((blockIdx.x & 1023) << 8) + threadIdx.x;
    const float* src = (w == 0) ? w0 : (w == 1) ? w1 : (w == 2) ? w2 : w3;
    float4 v = ((const float4*)src)[i];
    uint32_t h0,l0,h1,l1,h2,l2,h3,l3;
    cvt_split(v.x, h0, l0); cvt_split(v.y, h1, l1);
    cvt_split(v.z, h2, l2); cvt_split(v.w, h3, l3);
    size_t o = (size_t)w*262144 + i;
    ((uint2*)hi)[o] = make_uint2(h0 | (h1<<16), h2 | (h3<<16));
    ((uint2*)lo)[o] = make_uint2(l0 | (l1<<16), l2 | (l3<<16));
}

// ---------------- RMSNorm -> split bf16 --------------------------------------
__global__ void rms_kernel(const float* __restrict__ x, const float* __restrict__ w,
                           __nv_bfloat16* __restrict__ ohi,
                           __nv_bfloat16* __restrict__ olo) {
    __shared__ float red[8];
    int row = blockIdx.x;
    const float* xr = x + (size_t)row * D_;
    float v[4]; float ss = 0.f;
#pragma unroll
    for (int i = 0; i < 4; i++) { float t = xr[threadIdx.x + i*256]; v[i] = t; ss += t*t; }
#pragma unroll
    for (int o = 16; o; o >>= 1) ss += __shfl_xor_sync(0xffffffffu, ss, o);
    if ((threadIdx.x & 31) == 0) red[threadIdx.x >> 5] = ss;
    __syncthreads();
    float tot = 0.f;
#pragma unroll
    for (int i = 0; i < 8; i++) tot += red[i];
    float inv = rsqrtf(tot * (1.0f/1024.0f) + 1e-5f);
#pragma unroll
    for (int i = 0; i < 4; i++) {
        int c = threadIdx.x + i*256;
        float y = v[i] * inv * w[c];
        uint32_t h, l; cvt_split(y, h, l);
        ohi[(size_t)row*D_ + c] = __ushort_as_bfloat16((unsigned short)h);
        olo[(size_t)row*D_ + c] = __ushort_as_bfloat16((unsigned short)l);
    }
}

// ---------------- SiLU + RMSNorm -> split bf16 -------------------------------
__global__ void silu_rms_kernel(const float* __restrict__ x, const float* __restrict__ w,
                                __nv_bfloat16* __restrict__ ohi,
                                __nv_bfloat16* __restrict__ olo) {
    __shared__ float red[8];
    int row = blockIdx.x;
    const float* xr = x + (size_t)row * D_;
    float y[4]; float ss = 0.f;
#pragma unroll
    for (int i = 0; i < 4; i++) {
        float t = xr[threadIdx.x + i*256];
        float yy = t / (1.0f + __expf(-t));
        y[i] = yy; ss += yy*yy;
    }
#pragma unroll
    for (int o = 16; o; o >>= 1) ss += __shfl_xor_sync(0xffffffffu, ss, o);
    if ((threadIdx.x & 31) == 0) red[threadIdx.x >> 5] = ss;
    __syncthreads();
    float tot = 0.f;
#pragma unroll
    for (int i = 0; i < 8; i++) tot += red[i];
    float inv = rsqrtf(tot * (1.0f/1024.0f) + 1e-5f);
#pragma unroll
    for (int i = 0; i < 4; i++) {
        int c = threadIdx.x + i*256;
        float yv = y[i] * inv * w[c];
        uint32_t h, l; cvt_split(yv, h, l);
        ohi[(size_t)row*D_ + c] = __ushort_as_bfloat16((unsigned short)h);
        olo[(size_t)row*D_ + c] = __ushort_as_bfloat16((unsigned short)l);
    }
}

// ---------------- gate softmax over 256 --------------------------------------
__global__ void softmax_g_kernel(float* __restrict__ gm) {
    __shared__ float red[8];
    int row = blockIdx.x;
    float v = gm[(size_t)row*256 + threadIdx.x];
    float m = v;
#pragma unroll
    for (int o = 16; o; o >>= 1) m = fmaxf(m, __shfl_xor_sync(0xffffffffu, m, o));
    if ((threadIdx.x & 31) == 0) red[threadIdx.x >> 5] = m;
    __syncthreads();
    float mm = red[0];
#pragma unroll
    for (int i = 1; i < 8; i++) mm = fmaxf(mm, red[i]);
    float e = __expf(v - mm);
    float s = e;
#pragma unroll
    for (int o = 16; o; o >>= 1) s += __shfl_xor_sync(0xffffffffu, s, o);
    __syncthreads();
    if ((threadIdx.x & 31) == 0) red[threadIdx.x >> 5] = s;
    __syncthreads();
    float tot = 0.f;
#pragma unroll
    for (int i = 0; i < 8; i++) tot += red[i];
    gm[(size_t)row*256 + threadIdx.x] = e / tot;
}

// ---------------- HMMA split-bf16 GEMM: C[M,N] = A[M,K] @ W[N,K]^T -----------
// z = 0..3: projections (N=1024, C = Cb + z*cstride)
// z = 4:    gate (N=256, C = Cg, only blockIdx.x < 2 active)
#define GM_STRIDE 80
#define GM_ARR    10240
#define GM_STAGE  40960
#define GM_SMEM   81920

__global__ void __launch_bounds__(256, 2) gemm_mma(const __nv_bfloat16* __restrict__ Ah,
                                                   const __nv_bfloat16* __restrict__ Al,
                                                   const __nv_bfloat16* __restrict__ Bh,
                                                   const __nv_bfloat16* __restrict__ Bl,
                                                   float* __restrict__ Cb,
                                                   float* __restrict__ Cg,
                                                   size_t wstride, size_t cstride) {
    int N = 1024;
    float* C;
    if (blockIdx.z == 4) {
        if (blockIdx.x >= 2) return;
        N = 256;
        C = Cg;
    } else {
        C = Cb + (size_t)blockIdx.z * cstride;
    }
    extern __shared__ char smem[];
    uint32_t sb = smem_u32(smem);
    int tid = threadIdx.x;
    int lane = tid & 31, wid = tid >> 5;
    int wm = wid >> 2, wn = wid & 3;
    int m0 = blockIdx.y * 128, n0 = blockIdx.x * 128;
    size_t zo = (size_t)blockIdx.z * wstride;

    const __nv_bfloat16* srcs[4];
    srcs[0] = Ah + (size_t)m0*1024;
    srcs[1] = Al + (size_t)m0*1024;
    srcs[2] = Bh + zo + (size_t)n0*1024;
    srcs[3] = Bl + zo + (size_t)n0*1024;

    float acc[4][4][4];
#pragma unroll
    for (int i = 0; i < 4; i++)
#pragma unroll
        for (int j = 0; j < 4; j++)
#pragma unroll
            for (int e = 0; e < 4; e++) acc[i][j][e] = 0.f;

    int row_l = tid >> 2, c8 = tid & 3;

    {   // prologue: stage 0
        uint32_t base = sb;
#pragma unroll
        for (int arr = 0; arr < 4; arr++)
#pragma unroll
            for (int l = 0; l < 2; l++) {
                int row = row_l + l*64;
                cpasync16(base + arr*GM_ARR + row*GM_STRIDE + c8*16,
                          srcs[arr] + (size_t)row*1024 + c8*8);
            }
        CP_COMMIT();
    }

    for (int s = 0; s < 32; s++) {
        CP_WAIT0();
        __syncthreads();
        if (s + 1 < 32) {
            uint32_t base = sb + ((s+1) & 1)*GM_STAGE;
            int k0 = (s+1)*32;
#pragma unroll
            for (int arr = 0; arr < 4; arr++)
#pragma unroll
                for (int l = 0; l < 2; l++) {
                    int row = row_l + l*64;
                    cpasync16(base + arr*GM_ARR + row*GM_STRIDE + c8*16,
                              srcs[arr] + (size_t)row*1024 + k0 + c8*8);
                }
            CP_COMMIT();
        }
        uint32_t stb = sb + (s & 1)*GM_STAGE;
#pragma unroll
        for (int kk = 0; kk < 2; kk++) {
            uint32_t bh[4][2], bl[4][2];
            int rowB = wn*32 + ((lane >> 4) & 1)*8 + (lane & 7);
            int colB = kk*32 + ((lane >> 3) & 1)*16;
#pragma unroll
            for (int np = 0; np < 2; np++) {
                uint32_t rb = (rowB + np*16)*GM_STRIDE + colB;
                uint32_t r0,r1,r2,r3;
                ldsm4(r0, r1, r2, r3, stb + 2*GM_ARR + rb);
                bh[np*2][0] = r0; bh[np*2][1] = r1; bh[np*2+1][0] = r2; bh[np*2+1][1] = r3;
                ldsm4(r0, r1, r2, r3, stb + 3*GM_ARR + rb);
                bl[np*2][0] = r0; bl[np*2][1] = r1; bl[np*2+1][0] = r2; bl[np*2+1][1] = r3;
            }
            int colA = kk*32 + ((lane >> 4) & 1)*16;
            uint32_t ah[2][4], al[2][4];
            {
                uint32_t ra = (wm*64 + (lane & 15))*GM_STRIDE + colA;
                ldsm4(ah[0][0], ah[0][1], ah[0][2], ah[0][3], stb + ra);
                ldsm4(al[0][0], al[0][1], al[0][2], al[0][3], stb + GM_ARR + ra);
            }
#pragma unroll
            for (int mi = 0; mi < 4; mi++) {
                int cur = mi & 1;
                if (mi < 3) {
                    uint32_t ra = (wm*64 + (mi+1)*16 + (lane & 15))*GM_STRIDE + colA;
                    ldsm4(ah[cur^1][0], ah[cur^1][1], ah[cur^1][2], ah[cur^1][3], stb + ra);
                    ldsm4(al[cur^1][0], al[cur^1][1], al[cur^1][2], al[cur^1][3],
                          stb + GM_ARR + ra);
                }
#pragma unroll
                for (int nj = 0; nj < 4; nj++) {
                    mma16816(acc[mi][nj], ah[cur], bh[nj][0], bh[nj][1]);
                    mma16816(acc[mi][nj], ah[cur], bl[nj][0], bl[nj][1]);
                    mma16816(acc[mi][nj], al[cur], bh[nj][0], bh[nj][1]);
                }
            }
        }
        __syncthreads();
    }
#pragma unroll
    for (int mi = 0; mi < 4; mi++) {
        int r = m0 + wm*64 + mi*16 + (lane >> 2);
#pragma unroll
        for (int nj = 0; nj < 4; nj++) {
            int cc = n0 + wn*32 + nj*8 + (lane & 3)*2;
            *(float2*)(C + (size_t)r*N + cc)     = make_float2(acc[mi][nj][0], acc[mi][nj][1]);
            *(float2*)(C + (size_t)(r+8)*N + cc) = make_float2(acc[mi][nj][2], acc[mi][nj][3]);
        }
    }
}

// ---------------- per-chunk outer products (state sums) ----------------------
__global__ void __launch_bounds__(256) chunk_outer_kernel() {
    __shared__ float gsm[64*68];
    int id = blockIdx.x;
    int which = id >> 8;
    int sub = id & 255;
    int bh = sub >> 5, c = sub & 31;
    int b = bh >> 2, h = bh & 3;
    int tid = threadIdx.x;
    const float* gsrc = g_g + (size_t)(b*T_ + c*64)*256 + h*64;
#pragma unroll
    for (int e = 0; e < 16; e++) {
        int idx = tid + e*256; int u = idx >> 6, j = idx & 63;
        gsm[u*68 + j] = gsrc[(size_t)u*256 + j];
    }
    __syncthreads();
    ull acc2[32];
#pragma unroll
    for (int j = 0; j < 32; j++) acc2[j] = 0ull;
    const float* src = (which == 0)
        ? (GS + (size_t)(b*T_ + c*64)*D_ + h*256 + tid)
        : (GV + (size_t)(b*T_ + c*64)*D_ + h*256 + tid);
    for (int u = 0; u < 64; u++) {
        float sv = src[(size_t)u*D_];
        ull sd = pk2(sv, sv);
#pragma unroll
        for (int j4 = 0; j4 < 16; j4++) {
            float4 gg = *(const float4*)(gsm + u*68 + j4*4);
            ffma2(acc2[j4*2+0], sd, pk2(gg.x, gg.y));
            ffma2(acc2[j4*2+1], sd, pk2(gg.z, gg.w));
        }
    }
    if (which == 0) {
        float* dst = g_st1 + ((size_t)(bh*32 + c)*256 + tid)*64;
#pragma unroll
        for (int j2 = 0; j2 < 32; j2++) {
            float lo, hi; upk2(acc2[j2], lo, hi);
            *(float2*)(dst + j2*2) = make_float2(lo, hi);
        }
    } else {
        float* dst = g_st2 + (size_t)(bh*32 + c)*16384 + tid;
#pragma unroll
        for (int j2 = 0; j2 < 32; j2++) {
            float lo, hi; upk2(acc2[j2], lo, hi);
            dst[(size_t)(j2*2)*256]   = lo;
            dst[(size_t)(j2*2+1)*256] = hi;
        }
    }
}

// ---------------- exclusive scan over 32 chunks ------------------------------
__global__ void scan_kernel() {
    int gb = blockIdx.x;
    int which = gb >> 9;
    int sub = gb & 511;
    int bh = sub >> 6;
    int e = (sub & 63)*256 + threadIdx.x;
    float* base = which ? g_st2 : g_st1;
    float run = 0.f;
    for (int c = 0; c < 32; c++) {
        size_t idx = ((size_t)(bh*32 + c) << 14) + e;
        float t = base[idx]; base[idx] = run; run += t;
    }
}

// ---------------- attention helpers ------------------------------------------
__device__ __forceinline__ void ldT64(float* dst, const float* src, int lds_, int tid) {
#pragma unroll
    for (int e = 0; e < 16; e++) {
        int idx = tid + e*256; int r = idx >> 6, kk = idx & 63;
        dst[kk*68 + r] = src[(size_t)r*lds_ + kk];
    }
}
__device__ __forceinline__ void ldg16(float r[16], const float* src, int lds_, int tid) {
#pragma unroll
    for (int e = 0; e < 16; e++) {
        int idx = tid + e*256;
        r[e] = src[(size_t)(idx >> 6)*lds_ + (idx & 63)];
    }
}
__device__ __forceinline__ void sts16T(float* dst, const float r[16], int tid) {
#pragma unroll
    for (int e = 0; e < 16; e++) {
        int idx = tid + e*256;
        dst[(idx & 63)*68 + (idx >> 6)] = r[e];   // transposed store
    }
}
__device__ __forceinline__ void sts16D(float* dst, const float r[16], int tid) {
#pragma unroll
    for (int e = 0; e < 16; e++) {
        int idx = tid + e*256;
        dst[(idx >> 6)*68 + (idx & 63)] = r[e];   // direct store
    }
}
__device__ __forceinline__ void ldD64(float* dst, const float* src, int lds_, int tid) {
#pragma unroll
    for (int e = 0; e < 16; e++) {
        int idx = tid + e*256; int k = idx >> 6, j = idx & 63;
        dst[k*68 + j] = src[(size_t)k*lds_ + j];
    }
}
__device__ __forceinline__ void ldV(float* vsm, const float* src, int lds_, int tid) {
#pragma unroll
    for (int e = 0; e < 16; e++) {
        int idx = tid + e*256; int u = idx >> 6, c4 = idx & 63;
        *(float4*)(vsm + u*264 + c4*4) = *(const float4*)(src + (size_t)u*lds_ + c4*4);
    }
}
__device__ __forceinline__ void gemm16(ull acc2[4][2], const float* A, const float* Bq,
                                       int nk, int ty, int tx) {
    for (int k = 0; k < nk; k++) {
        float4 a4 = *(const float4*)(A  + k*68 + ty*4);
        float4 b4 = *(const float4*)(Bq + k*68 + tx*4);
        ull bp0 = pk2(b4.x, b4.y), bp1 = pk2(b4.z, b4.w);
        float a[4] = {a4.x, a4.y, a4.z, a4.w};
#pragma unroll
        for (int i = 0; i < 4; i++) {
            ull ad = pk2(a[i], a[i]);
            ffma2(acc2[i][0], ad, bp0);
            ffma2(acc2[i][1], ad, bp1);
        }
    }
}
__device__ __forceinline__ void unpk16(float dst[4][4], const ull a2[4][2]) {
#pragma unroll
    for (int i = 0; i < 4; i++) {
        upk2(a2[i][0], dst[i][0], dst[i][1]);
        upk2(a2[i][1], dst[i][2], dst[i][3]);
    }
}
__device__ __forceinline__ void pv_acc(ull o2[4][4][2], const float* P, const float* V,
                                       int ty, int tx) {
    for (int u = 0; u < 64; u++) {
        float4 p4 = *(const float4*)(P + u*68 + ty*4);
        ull pd[4];
        pd[0] = pk2(p4.x, p4.x); pd[1] = pk2(p4.y, p4.y);
        pd[2] = pk2(p4.z, p4.z); pd[3] = pk2(p4.w, p4.w);
#pragma unroll
        for (int j = 0; j < 4; j++) {
            float4 v4 = *(const float4*)(V + u*264 + tx*4 + j*64);
            ull vp0 = pk2(v4.x, v4.y), vp1 = pk2(v4.z, v4.w);
#pragma unroll
            for (int i = 0; i < 4; i++) {
                ffma2(o2[i][j][0], pd[i], vp0);
                ffma2(o2[i][j][1], pd[i], vp1);
            }
        }
    }
}
__device__ __forceinline__ float rowmax4(const float* arr, int r, int seg) {
    float v = -3.4e38f;
#pragma unroll
    for (int uu = 0; uu < 16; uu++) v = fmaxf(v, arr[(seg*16+uu)*68 + r]);
    v = fmaxf(v, __shfl_xor_sync(0xffffffffu, v, 1));
    v = fmaxf(v, __shfl_xor_sync(0xffffffffu, v, 2));
    return v;
}
__device__ __forceinline__ float rowsum4(const float* arr, int r, int seg) {
    float v = 0.f;
#pragma unroll
    for (int uu = 0; uu < 16; uu++) v += arr[(seg*16+uu)*68 + r];
    v += __shfl_xor_sync(0xffffffffu, v, 1);
    v += __shfl_xor_sync(0xffffffffu, v, 2);
    return v;
}

// smem: qsT 17408 | Bs0 4352 | Bs1 4352 | psh 4352 | sst 4352 | vsm 16896 | 192
#define SMEM_ATTN (51904*4)

// ---------------- fused attention: grid 256 (bh*32 + tile), 256 threads ------
__global__ void __launch_bounds__(256) attn_kernel() {
    extern __shared__ float sm[];
    float* qsT  = sm;
    float* Bs   = qsT + 256*68;          // double buffer: Bs, Bs+4352
    float* psh  = Bs  + 2*64*68;
    float* sst  = psh + 64*68;
    float* vsm  = sst + 64*68;
    float* mrow = vsm + 64*264;
    float* zrow = mrow + 64;
    float* frow = zrow + 64;

    int tid = threadIdx.x;
    int tx = tid & 15, ty = tid >> 4;
    int tile = blockIdx.x & 31, bh = blockIdx.x >> 5;
    int b = bh >> 2, h = bh & 3;
    int t0 = tile*64;
    float slope = exp2f(-2.0f*(float)h);
    int r4 = tid >> 2, seg = tid & 3;

    const float* qbase = GQ + (size_t)(b*T_ + t0)*D_ + h*256;
    const float* sbase = GS + (size_t)(b*T_ + t0)*D_ + h*256;
    const float* gbase = g_g + (size_t)(b*T_ + t0)*256 + h*64;
    const float* kbase = GK + (size_t)(b*T_)*D_ + h*256;
    const float* vbase = GV + (size_t)(b*T_)*D_ + h*256;
    const float* st1   = g_st1 + (size_t)(bh*32 + tile)*16384;
    const float* st2   = g_st2 + (size_t)(bh*32 + tile)*16384;

    for (int ks = 0; ks < 4; ks++) ldT64(qsT + ks*64*68, qbase + ks*64, D_, tid);

    ull acc2[4][2];
    float acc[4][4];
    // ---- A_intra = mask(q @ s^T), pipelined s loads (transposed stores) ----
#pragma unroll
    for (int i = 0; i < 4; i++) { acc2[i][0] = 0ull; acc2[i][1] = 0ull; }
    {
        float bufr[2][16];
        ldg16(bufr[0], sbase, D_, tid);
#pragma unroll
        for (int ks = 0; ks < 4; ks++) {
            if (ks < 3) ldg16(bufr[(ks+1)&1], sbase + (ks+1)*64, D_, tid);
            sts16T(Bs + (ks&1)*4352, bufr[ks&1], tid);
            __syncthreads();
            gemm16(acc2, qsT + ks*64*68, Bs + (ks&1)*4352, 64, ty, tx);
        }
    }
    unpk16(acc, acc2);
    __syncthreads();
#pragma unroll
    for (int i = 0; i < 4; i++)
#pragma unroll
        for (int j = 0; j < 4; j++) {
            int r = ty*4+i, uu = tx*4+j;
            psh[uu*68 + r] = (uu <= r) ? acc[i][j] : 0.f;
        }
    __syncthreads();
    // ---- sc_state = A_intra @ g + q @ St1prefix ----
#pragma unroll
    for (int i = 0; i < 4; i++) { acc2[i][0] = 0ull; acc2[i][1] = 0ull; }
    ldD64(Bs, gbase, 256, tid);
    __syncthreads();
    gemm16(acc2, psh, Bs, 64, ty, tx);
    {
        float bufr[2][16];
        ldg16(bufr[0], st1, 64, tid);
#pragma unroll
        for (int ks = 0; ks < 4; ks++) {
            if (ks < 3) ldg16(bufr[(ks+1)&1], st1 + (ks+1)*64*64, 64, tid);
            __syncthreads();
            sts16D(Bs + (ks&1)*4352, bufr[ks&1], tid);   // direct store
            __syncthreads();
            gemm16(acc2, qsT + ks*64*68, Bs + (ks&1)*4352, 64, ty, tx);
        }
    }
    unpk16(acc, acc2);
    __syncthreads();
#pragma unroll
    for (int i = 0; i < 4; i++)
#pragma unroll
        for (int j = 0; j < 4; j++)
            sst[(tx*4+j)*68 + ty*4+i] = acc[i][j];
    __syncthreads();
    {
        float mx = rowmax4(sst, r4, seg);
        if (seg == 0) { mrow[r4] = mx; zrow[r4] = 0.f; }
    }
    ull o2[4][4][2];
#pragma unroll
    for (int i = 0; i < 4; i++)
#pragma unroll
        for (int j = 0; j < 4; j++) { o2[i][j][0] = 0ull; o2[i][j][1] = 0ull; }
    __syncthreads();

    // ---- sliding-window chunks, pipelined K loads ----
    for (int ci = 0; ci < 9; ci++) {
        int u0 = t0 - 512 + ci*64;
        if (u0 < 0) continue;
#pragma unroll
        for (int i = 0; i < 4; i++) { acc2[i][0] = 0ull; acc2[i][1] = 0ull; }
        {
            const float* kc = kbase + (size_t)u0*D_;
            float bufr[2][16];
            ldg16(bufr[0], kc, D_, tid);
#pragma unroll
            for (int ks = 0; ks < 4; ks++) {
                if (ks < 3) ldg16(bufr[(ks+1)&1], kc + (ks+1)*64, D_, tid);
                sts16T(Bs + (ks&1)*4352, bufr[ks&1], tid);
                __syncthreads();
                gemm16(acc2, qsT + ks*64*68, Bs + (ks&1)*4352, 64, ty, tx);
            }
        }
        unpk16(acc, acc2);
        __syncthreads();
#pragma unroll
        for (int i = 0; i < 4; i++)
#pragma unroll
            for (int j = 0; j < 4; j++) {
                int r = ty*4+i, uu = tx*4+j;
                int d = t0 + r - u0 - uu;
                psh[uu*68 + r] = (d >= 0 && d < 512) ? acc[i][j] - slope*(float)d : -1e30f;
            }
        __syncthreads();
        {
            float cm = rowmax4(psh, r4, seg);
            if (seg == 0) {
                float mo = mrow[r4], mn = fmaxf(mo, cm);
                frow[r4] = __expf(mo - mn); mrow[r4] = mn;
            }
        }
        __syncthreads();
#pragma unroll
        for (int e = 0; e < 16; e++) {
            int idx = tid + e*256; int uu = idx >> 6, r = idx & 63;
            psh[uu*68 + r] = __expf(psh[uu*68 + r] - mrow[r]);
        }
        __syncthreads();
        {
            float cz = rowsum4(psh, r4, seg);
            if (seg == 0) zrow[r4] = zrow[r4]*frow[r4] + cz;
        }
        ldV(vsm, vbase + (size_t)u0*D_, D_, tid);
        __syncthreads();
#pragma unroll
        for (int i = 0; i < 4; i++) {
            float f = frow[ty*4 + i];
            ull fd = pk2(f, f);
#pragma unroll
            for (int j = 0; j < 4; j++) {
                fmul2(o2[i][j][0], fd); fmul2(o2[i][j][1], fd);
            }
        }
        pv_acc(o2, psh, vsm, ty, tx);
    }
    __syncthreads();
    // ---- fold in state scores, finalize softmax ----
#pragma unroll
    for (int e = 0; e < 16; e++) {
        int idx = tid + e*256; int j = idx >> 6, r = idx & 63;
        sst[j*68 + r] = __expf(sst[j*68 + r] - mrow[r]);
    }
    __syncthreads();
    {
        float zs = rowsum4(sst, r4, seg);
        if (seg == 0) frow[r4] = 1.0f / (zrow[r4] + zs);
    }
    __syncthreads();
#pragma unroll
    for (int e = 0; e < 16; e++) {
        int idx = tid + e*256; int j = idx >> 6, r = idx & 63;
        sst[j*68 + r] *= frow[r];
    }
#pragma unroll
    for (int i = 0; i < 4; i++) {
        float fi = frow[ty*4 + i];
        ull fd = pk2(fi, fi);
#pragma unroll
        for (int j = 0; j < 4; j++) {
            fmul2(o2[i][j][0], fd); fmul2(o2[i][j][1], fd);
        }
    }
    ldV(vsm, st2, 256, tid);
    ldT64(Bs, gbase, 256, tid);
    __syncthreads();
    pv_acc(o2, sst, vsm, ty, tx);
#pragma unroll
    for (int i = 0; i < 4; i++) { acc2[i][0] = 0ull; acc2[i][1] = 0ull; }
    gemm16(acc2, sst, Bs, 64, ty, tx);
    unpk16(acc, acc2);
    __syncthreads();
#pragma unroll
    for (int i = 0; i < 4; i++)
#pragma unroll
        for (int j = 0; j < 4; j++) {
            int r = ty*4+i, uu = tx*4+j;
            psh[uu*68 + r] = (uu <= r) ? acc[i][j] : 0.f;
        }
    ldV(vsm, vbase + (size_t)t0*D_, D_, tid);
    __syncthreads();
    pv_acc(o2, psh, vsm, ty, tx);
    float* obase = g_o + (size_t)(b*T_ + t0)*D_ + h*256;
#pragma unroll
    for (int i = 0; i < 4; i++) {
        float* dst = obase + (size_t)(ty*4+i)*D_;
#pragma unroll
        for (int j = 0; j < 4; j++) {
            float x0,x1,x2,x3;
            upk2(o2[i][j][0], x0, x1);
            upk2(o2[i][j][1], x2, x3);
            *(float4*)(dst + tx*4 + j*64) = make_float4(x0,x1,x2,x3);
        }
    }
}

// ---------------- launch -----------------------------------------------------
extern "C" void kernel_launch(void* const* d_in, const int* in_sizes, int n_in,
                              void* d_out, int out_size) {
    const float* hidden = (const float*)d_in[0];
    const float* wnorm  = (const float*)d_in[1];
    const float* Wq = (const float*)d_in[2];
    const float* Wk = (const float*)d_in[3];
    const float* Wv = (const float*)d_in[4];
    const float* Ws = (const float*)d_in[5];
    const float* Wg = (const float*)d_in[6];
    const float* Wo = (const float*)d_in[7];
    float* out = (float*)d_out;

    float *pproj, *pg, *po;
    __nv_bfloat16 *phh, *phl, *pwh, *pwl;
    cudaGetSymbolAddress((void**)&pproj, g_proj);
    cudaGetSymbolAddress((void**)&pg, g_g);
    cudaGetSymbolAddress((void**)&po, g_o);
    cudaGetSymbolAddress((void**)&phh, g_hh);
    cudaGetSymbolAddress((void**)&phl, g_hl);
    cudaGetSymbolAddress((void**)&pwh, g_wh);
    cudaGetSymbolAddress((void**)&pwl, g_wl);

    cudaFuncSetAttribute(attn_kernel, cudaFuncAttributeMaxDynamicSharedMemorySize, SMEM_ATTN);
    cudaFuncSetAttribute(gemm_mma, cudaFuncAttributeMaxDynamicSharedMemorySize, GM_SMEM);

    const size_t WSLOT = (size_t)D_*D_;       // 1048576 elems
    const size_t CSLOT = (size_t)BT_*D_;      // 4194304 elems

    // slots: 0-3 = Wq Wk Wv Ws, 4 = Wg, 5 = Wo
    rms_kernel<<<BT_, 256>>>(hidden, wnorm, phh, phl);                            // 1
    split4_kernel<<<4096, 256>>>(Wq, Wk, Wv, Ws, pwh, pwl);                       // 2
    split_kernel<<<256, 256>>>(Wg, pwh + 4*WSLOT, pwl + 4*WSLOT);                 // 3
    gemm_mma<<<dim3(8,32,5), 256, GM_SMEM>>>(phh, phl, pwh, pwl,                  // 4 (ncu)
                                             pproj, pg, WSLOT, CSLOT);
    softmax_g_kernel<<<BT_, 256>>>(pg);                                           // 5
    chunk_outer_kernel<<<512, 256>>>();                                           // 6
    scan_kernel<<<1024, 256>>>();                                                 // 7
    attn_kernel<<<256, 256, SMEM_ATTN>>>();                                       // 8
    split_kernel<<<1024, 256>>>(Wo, pwh + 5*WSLOT, pwl + 5*WSLOT);                // 9
    silu_rms_kernel<<<BT_, 256>>>(po, wnorm, phh, phl);                           // 10
    gemm_mma<<<dim3(8,32,1), 256, GM_SMEM>>>(phh, phl, pwh + 5*WSLOT, pwl + 5*WSLOT,
                                             out, pg /*unused*/, 0, 0);           // 11
}